// round 17
// baseline (speedup 1.0000x reference)
#include <cuda_runtime.h>
#include <cuda_bf16.h>
#include <cstdint>

#define NN 50000
#define FF 64
#define HH 128
#define GG 512
#define BN_EPSF 1e-3f
#define PAD 96                       // max supported degree per node
#define TILE 64
#define NT2 (50048 / TILE)           // 782 tiles of 64 rows

// ---------------- scratch (device globals; no dynamic alloc allowed) ----------
static __device__ float    g_a[NN * HH];   // A = h @ (W1-W2) + b_cn  (fp32)
static __device__ unsigned g_bh[NN * 64];  // B = h @ W2 as bf16x2 pairs
static __device__ float    g_p[GG * HH];   // pooled per-graph sums
static __device__ float    g_y2[GG * HH];  // post-GEMM output (pre-BN)
static __device__ float    g_gram[FF * FF];// x^T x
static __device__ float    g_colsum[FF];   // column sums of x
static __device__ double   g_sum2[HH];
static __device__ double   g_sumsq2[HH];
// padded adjacency
static __device__ int      g_cnt[NN];          // degree (atomic cursor)
static __device__ int      g_adj[NN * PAD];    // dst per edge, grouped by src

// ---------------- PTX helpers ---------------
__device__ __forceinline__ uint32_t smem_u32(const void* p) {
    uint32_t a;
    asm("{ .reg .u64 t; cvta.to.shared.u64 t, %1; cvt.u32.u64 %0, t; }"
        : "=r"(a) : "l"(p));
    return a;
}

#define LDSM_X4(r0, r1, r2, r3, addr)                                          \
    asm volatile("ldmatrix.sync.aligned.m8n8.x4.shared.b16 {%0,%1,%2,%3}, [%4];" \
                 : "=r"(r0), "=r"(r1), "=r"(r2), "=r"(r3) : "r"(addr))

#define LDSM_X2T(r0, r1, addr)                                                 \
    asm volatile("ldmatrix.sync.aligned.m8n8.x2.trans.shared.b16 {%0,%1}, [%2];" \
                 : "=r"(r0), "=r"(r1) : "r"(addr))

#define MMA16816(d0, d1, d2, d3, a0, a1, a2, a3, b0, b1)                       \
    asm volatile("mma.sync.aligned.m16n8k16.row.col.f32.bf16.bf16.f32 "        \
                 "{%0,%1,%2,%3}, {%4,%5,%6,%7}, {%8,%9}, {%0,%1,%2,%3};"       \
                 : "+f"(d0), "+f"(d1), "+f"(d2), "+f"(d3)                      \
                 : "r"(a0), "r"(a1), "r"(a2), "r"(a3), "r"(b0), "r"(b1))

#define CP_ASYNC16(dst, src)                                                   \
    asm volatile("cp.async.ca.shared.global [%0], [%1], 16;"                   \
                 :: "r"(dst), "l"(src))
#define CP_COMMIT() asm volatile("cp.async.commit_group;" ::: "memory")
#define CP_WAIT0()  asm volatile("cp.async.wait_group 0;" ::: "memory")

__device__ __forceinline__ void split_pack(float a0, float a1,
                                           unsigned& hp, unsigned& lp) {
    asm("cvt.rn.bf16x2.f32 %0, %1, %2;" : "=r"(hp) : "f"(a1), "f"(a0));
    float h0 = __uint_as_float(hp << 16);
    float h1 = __uint_as_float(hp & 0xffff0000u);
    float l0 = a0 - h0, l1 = a1 - h1;
    asm("cvt.rn.bf16x2.f32 %0, %1, %2;" : "=r"(lp) : "f"(l1), "f"(l0));
}

// ---------------- zero: everything -------------------------------------------
__global__ void kzero() {
    int t = blockIdx.x * blockDim.x + threadIdx.x;
    if (t < GG * HH) g_p[t] = 0.f;
    if (t < NN) g_cnt[t] = 0;
    if (t < FF * FF) g_gram[t] = 0.f;
    if (t < FF) g_colsum[t] = 0.f;
    if (t < HH) { g_sum2[t] = 0.0; g_sumsq2[t] = 0.0; }
}

// ---------------- adjacency build: single pass, padded slots -----------------
__global__ void kscat2(const int* __restrict__ src, const int* __restrict__ dst,
                       int E) {
    int base = (blockIdx.x * blockDim.x + threadIdx.x) * 8;
#pragma unroll
    for (int u = 0; u < 8; u++) {
        int e = base + u;
        if (e < E) {
            int s = __ldg(src + e);
            int pos = atomicAdd(&g_cnt[s], 1);
            if (pos < PAD) g_adj[s * PAD + pos] = __ldg(dst + e);
        }
    }
}

// ---------------- kstat: G = x^T x (64x64) and colsum(x) ---------------------
__global__ void __launch_bounds__(256) kstat(const float* __restrict__ x) {
    __shared__ __align__(16) float xr[8][68];
    const int t = threadIdx.x;
    const int ti = (t & 15) * 4, tj = (t >> 4) * 4;
    float acc[4][4];
#pragma unroll
    for (int i = 0; i < 4; i++)
#pragma unroll
        for (int j = 0; j < 4; j++) acc[i][j] = 0.f;
    float cs = 0.f;
    const int rbase = blockIdx.x * 128;
    for (int it = 0; it < 16; it++) {
        __syncthreads();
        for (int idx = t; idx < 8 * FF; idx += 256) {
            int r = idx >> 6, c = idx & 63;
            int row = rbase + it * 8 + r;
            xr[r][c] = (row < NN) ? x[row * FF + c] : 0.f;
        }
        __syncthreads();
#pragma unroll
        for (int r = 0; r < 8; r++) {
            float4 a = *(const float4*)&xr[r][ti];
            float4 b = *(const float4*)&xr[r][tj];
            const float* av = (const float*)&a;
            const float* bv = (const float*)&b;
#pragma unroll
            for (int i = 0; i < 4; i++)
#pragma unroll
                for (int j = 0; j < 4; j++)
                    acc[i][j] = fmaf(av[i], bv[j], acc[i][j]);
        }
        if (t < FF) {
#pragma unroll
            for (int r = 0; r < 8; r++) cs += xr[r][t];
        }
    }
#pragma unroll
    for (int i = 0; i < 4; i++)
#pragma unroll
        for (int j = 0; j < 4; j++)
            atomicAdd(&g_gram[(ti + i) * FF + tj + j], acc[i][j]);
    if (t < FF) atomicAdd(&g_colsum[t], cs);
}

// ---------------- kfused: x -> y0 -> BN/relu -> dual GEMM --------------------
// smem: ws (dual W split, persistent) | union (wps fp32 / wp split / xs split)
//       | xraw (x tile fp32; also G stage during setup)
#define WS_STRIDE 528
#define WS_BYTES (128 * WS_STRIDE)        // 67584 each
#define UNI_OFF (2 * WS_BYTES)            // 135168
#define UNI_BYTES 34816
#define XRAW_OFF (UNI_OFF + UNI_BYTES)    // 169984
#define XRAW_BYTES (TILE * 68 * 4)        // 17408
#define KF_SMEM (XRAW_OFF + XRAW_BYTES)   // 187392
#define XS_STRIDE 144
#define HS_STRIDE 272

__global__ void __launch_bounds__(512) kfused(
    const float* __restrict__ x,
    const float* __restrict__ wpre,
    const float* __restrict__ gpre,  const float* __restrict__ bepre,
    const float* __restrict__ wcn,   const float* __restrict__ bcn) {
    extern __shared__ __align__(16) char smem[];
    char*  ws_hi = smem;
    char*  ws_lo = smem + WS_BYTES;
    char*  uni   = smem + UNI_OFF;
    float* xraw  = (float*)(smem + XRAW_OFF);
    __shared__ float hscale[HH], hbias[HH], bcn_s[HH], red[HH];
    const int t = threadIdx.x;
    const int lane = t & 31, wid = t >> 5;

    // ---- setup: stage wpre fp32 + G, stage dual-W split ----
    if (t < HH) red[t] = 0.f;
    float* wps = (float*)uni;
    float* Gs  = xraw;
    for (int idx = t; idx < FF * HH; idx += 512) wps[idx] = wpre[idx];
    for (int idx = t; idx < FF * FF; idx += 512) Gs[idx] = g_gram[idx];
    for (int idx = t; idx < HH * 256; idx += 512) {
        int k = idx >> 8, n = idx & 255;
        float w2 = wcn[(k + HH) * HH + (n & 127)];
        float v = (n < HH) ? (wcn[k * HH + n] - w2) : w2;
        __nv_bfloat16 hi = __float2bfloat16(v);
        float lo = v - __bfloat162float(hi);
        *(__nv_bfloat16*)(ws_hi + k * WS_STRIDE + n * 2) = hi;
        *(__nv_bfloat16*)(ws_lo + k * WS_STRIDE + n * 2) = __float2bfloat16(lo);
    }
    __syncthreads();

    // ---- wGw partials: thread (c = t&127, q = t>>7 owns 16 i's) ----
    {
        int c = t & 127, q = t >> 7;
        float wi[16];
#pragma unroll
        for (int i = 0; i < 16; i++) wi[i] = wps[(q * 16 + i) * HH + c];
        float acc = 0.f;
        for (int j = 0; j < FF; j++) {
            float wj = wps[j * HH + c];
            float gs = 0.f;
#pragma unroll
            for (int i = 0; i < 16; i++)
                gs = fmaf(wi[i], Gs[(q * 16 + i) * FF + j], gs);
            acc = fmaf(gs, wj, acc);
        }
        atomicAdd(&red[c], acc);
    }
    __syncthreads();
    if (t < HH) {
        float sdot = 0.f;
        for (int j = 0; j < FF; j++) sdot = fmaf(g_colsum[j], wps[j * HH + t], sdot);
        float mu0 = sdot * (1.f / NN);
        float var = red[t] * (1.f / NN) - mu0 * mu0;
        float sc  = gpre[t] * rsqrtf(var + BN_EPSF);
        hscale[t] = sc;
        hbias[t]  = bepre[t] - mu0 * sc;   // b_pre cancels in training-mode BN
        bcn_s[t]  = bcn[t];
    }
    __syncthreads();

    // ---- overwrite union with wpre split (bf16 hi/lo, stride 272) ----
    char* wp_hi = uni;
    char* wp_lo = uni + 17408;
    for (int idx = t; idx < FF * HH; idx += 512) {
        int k = idx >> 7, n = idx & 127;
        float v = wpre[idx];
        __nv_bfloat16 hi = __float2bfloat16(v);
        float lo = v - __bfloat162float(hi);
        *(__nv_bfloat16*)(wp_hi + k * HS_STRIDE + n * 2) = hi;
        *(__nv_bfloat16*)(wp_lo + k * HS_STRIDE + n * 2) = __float2bfloat16(lo);
    }
    __syncthreads();

    // ---- preload fragments: dual bhi (persistent) + wp hi/lo (persistent) ----
    const uint32_t wshi_base = smem_u32(ws_hi);
    const uint32_t wslo_base = smem_u32(ws_lo);
    const uint32_t uni_base  = smem_u32(uni);
    const int n0w = wid * 16;
    uint32_t bhi[8][2][2];
#pragma unroll
    for (int ks = 0; ks < 8; ks++)
#pragma unroll
        for (int nt = 0; nt < 2; nt++) {
            uint32_t roff = (ks * 16 + (lane & 15)) * WS_STRIDE + (n0w + nt * 8) * 2;
            LDSM_X2T(bhi[ks][nt][0], bhi[ks][nt][1], wshi_base + roff);
        }
    uint32_t wph[4][2], wpl[4][2];
#pragma unroll
    for (int ks = 0; ks < 4; ks++) {
        uint32_t roff = (ks * 16 + (lane & 15)) * HS_STRIDE + (wid * 8) * 2;
        LDSM_X2T(wph[ks][0], wph[ks][1], uni_base + roff);
        LDSM_X2T(wpl[ks][0], wpl[ks][1], uni_base + 17408 + roff);
    }
    __syncthreads();   // union free -> xs region from here

    // xs in union region; hs separate? hs overlays: xs at uni+0 (2x9216), hs... 
    // layout: xs_hi uni+0, xs_lo uni+9216; hs_hi/hs_lo need 2x17408 -> use
    // xs region + remainder: hs written AFTER x-MMA reads (separate phase).
    // To avoid races we keep hs in the SAME union region but only write after
    // a sync that ends all xs reads.
    const uint32_t xshi_base = uni_base;
    const uint32_t xslo_base = uni_base + 9216;
    const uint32_t hshi_base = uni_base;          // overwrites xs (post-sync)
    const uint32_t hslo_base = uni_base + 17408;
    char* hs_hi_c = uni;
    char* hs_lo_c = uni + 17408;
    const uint32_t xr_base = smem_u32(xraw);
    const int g = lane >> 2, tig = lane & 3;

    // prologue: load first tile
    int tile = blockIdx.x;
    if (tile < NT2) {
#pragma unroll
        for (int i = 0; i < 2; i++) {
            int idx = t + i * 512;           // 0..1023
            int row = idx >> 4, kg = idx & 15;
            int grow = min(tile * TILE + row, NN - 1);
            CP_ASYNC16(xr_base + (row * 68 + kg * 4) * 4, &x[grow * FF + kg * 4]);
        }
    }
    CP_COMMIT();
    CP_WAIT0();
    __syncthreads();

    for (; tile < NT2; tile += 148) {
        const int rbase = tile * TILE;
        // Phase A: split x tile -> xs (bf16 hi/lo)
        {
            int row = t >> 3;
            int k0 = (t & 7) * 8;
            const float* xp = &xraw[row * 68 + k0];
            float4 x0 = *(const float4*)xp;
            float4 x1 = *(const float4*)(xp + 4);
            uint4 pk_hi, pk_lo;
            unsigned* ph = (unsigned*)&pk_hi;
            unsigned* pl = (unsigned*)&pk_lo;
            split_pack(x0.x, x0.y, ph[0], pl[0]);
            split_pack(x0.z, x0.w, ph[1], pl[1]);
            split_pack(x1.x, x1.y, ph[2], pl[2]);
            split_pack(x1.z, x1.w, ph[3], pl[3]);
            uint32_t soff = row * XS_STRIDE + k0 * 2;
            *(uint4*)(smem + UNI_OFF + soff) = pk_hi;
            *(uint4*)(smem + UNI_OFF + 9216 + soff) = pk_lo;
        }
        __syncthreads();

        // Phase B: prefetch next x tile (overlaps MMA)
        int nxt = tile + 148;
        if (nxt < NT2) {
#pragma unroll
            for (int i = 0; i < 2; i++) {
                int idx = t + i * 512;
                int row = idx >> 4, kg = idx & 15;
                int grow = min(nxt * TILE + row, NN - 1);
                CP_ASYNC16(xr_base + (row * 68 + kg * 4) * 4, &x[grow * FF + kg * 4]);
            }
        }
        CP_COMMIT();

        // Phase C: x-MMA -> y fragments (kept in regs; 4 mt x 4 regs)
        float yv[4][4];
#pragma unroll 1
        for (int mt = 0; mt < 4; mt++) {
            float yh[4] = {0.f, 0.f, 0.f, 0.f};
            float yl[4] = {0.f, 0.f, 0.f, 0.f};
#pragma unroll
            for (int ks = 0; ks < 4; ks++) {
                uint32_t a0, a1, a2, a3, l0, l1, l2, l3;
                uint32_t roff = (mt * 16 + (lane & 15)) * XS_STRIDE
                              + ks * 32 + (lane & 16);
                LDSM_X4(a0, a1, a2, a3, xshi_base + roff);
                LDSM_X4(l0, l1, l2, l3, xslo_base + roff);
                MMA16816(yh[0], yh[1], yh[2], yh[3], a0, a1, a2, a3,
                         wph[ks][0], wph[ks][1]);
                MMA16816(yl[0], yl[1], yl[2], yl[3], l0, l1, l2, l3,
                         wph[ks][0], wph[ks][1]);
                MMA16816(yl[0], yl[1], yl[2], yl[3], a0, a1, a2, a3,
                         wpl[ks][0], wpl[ks][1]);
            }
#pragma unroll
            for (int r = 0; r < 4; r++) yv[mt][r] = yh[r] + yl[r];
        }
        __syncthreads();   // all xs reads done; union becomes hs

        // Phase D: BN + relu + split -> hs
        {
            const int cy = wid * 8 + tig * 2;
            const float sc0 = hscale[cy], sc1 = hscale[cy + 1];
            const float hb0 = hbias[cy],  hb1 = hbias[cy + 1];
#pragma unroll
            for (int mt = 0; mt < 4; mt++) {
                int r0 = mt * 16 + g, r1 = r0 + 8;
                float v0 = fmaxf(fmaf(yv[mt][0], sc0, hb0), 0.f);
                float v1 = fmaxf(fmaf(yv[mt][1], sc1, hb1), 0.f);
                unsigned hp, lp;
                split_pack(v0, v1, hp, lp);
                *(unsigned*)(hs_hi_c + r0 * HS_STRIDE + cy * 2) = hp;
                *(unsigned*)(hs_lo_c + r0 * HS_STRIDE + cy * 2) = lp;
                v0 = fmaxf(fmaf(yv[mt][2], sc0, hb0), 0.f);
                v1 = fmaxf(fmaf(yv[mt][3], sc1, hb1), 0.f);
                split_pack(v0, v1, hp, lp);
                *(unsigned*)(hs_hi_c + r1 * HS_STRIDE + cy * 2) = hp;
                *(unsigned*)(hs_lo_c + r1 * HS_STRIDE + cy * 2) = lp;
            }
        }
        __syncthreads();

        // Phase E: dual GEMM (reload blo per tile; live range limited to E)
        uint32_t blo[8][2][2];
#pragma unroll
        for (int ks = 0; ks < 8; ks++)
#pragma unroll
            for (int nt = 0; nt < 2; nt++) {
                uint32_t roff = (ks * 16 + (lane & 15)) * WS_STRIDE
                              + (n0w + nt * 8) * 2;
                LDSM_X2T(blo[ks][nt][0], blo[ks][nt][1], wslo_base + roff);
            }
#pragma unroll 1
        for (int mt = 0; mt < 4; mt++) {
            float dh[2][4], dl[2][4];
#pragma unroll
            for (int nt = 0; nt < 2; nt++)
#pragma unroll
                for (int r = 0; r < 4; r++) { dh[nt][r] = 0.f; dl[nt][r] = 0.f; }
#pragma unroll
            for (int ks = 0; ks < 8; ks++) {
                uint32_t a0, a1, a2, a3, l0, l1, l2, l3;
                uint32_t roff = (mt * 16 + (lane & 15)) * HS_STRIDE
                              + ks * 32 + (lane & 16);
                LDSM_X4(a0, a1, a2, a3, hshi_base + roff);
                LDSM_X4(l0, l1, l2, l3, hslo_base + roff);
#pragma unroll
                for (int nt = 0; nt < 2; nt++) {
                    MMA16816(dh[nt][0], dh[nt][1], dh[nt][2], dh[nt][3],
                             a0, a1, a2, a3, bhi[ks][nt][0], bhi[ks][nt][1]);
                    MMA16816(dl[nt][0], dl[nt][1], dl[nt][2], dl[nt][3],
                             l0, l1, l2, l3, bhi[ks][nt][0], bhi[ks][nt][1]);
                    MMA16816(dl[nt][0], dl[nt][1], dl[nt][2], dl[nt][3],
                             a0, a1, a2, a3, blo[ks][nt][0], blo[ks][nt][1]);
                }
            }
            const int r0 = rbase + mt * 16 + g;
            const int r1 = r0 + 8;
#pragma unroll
            for (int nt = 0; nt < 2; nt++) {
                int c = n0w + nt * 8 + tig * 2;
                float s0 = dh[nt][0] + dl[nt][0];
                float s1 = dh[nt][1] + dl[nt][1];
                float s2 = dh[nt][2] + dl[nt][2];
                float s3 = dh[nt][3] + dl[nt][3];
                if (c < HH) {
                    float2 v0 = make_float2(s0 + bcn_s[c], s1 + bcn_s[c + 1]);
                    float2 v1 = make_float2(s2 + bcn_s[c], s3 + bcn_s[c + 1]);
                    if (r0 < NN) *(float2*)&g_a[r0 * HH + c] = v0;
                    if (r1 < NN) *(float2*)&g_a[r1 * HH + c] = v1;
                } else {
                    unsigned p0, p1;
                    asm("cvt.rn.bf16x2.f32 %0, %1, %2;" : "=r"(p0) : "f"(s1), "f"(s0));
                    asm("cvt.rn.bf16x2.f32 %0, %1, %2;" : "=r"(p1) : "f"(s3), "f"(s2));
                    int cb = (c - HH) >> 1;
                    if (r0 < NN) g_bh[r0 * 64 + cb] = p0;
                    if (r1 < NN) g_bh[r1 * 64 + cb] = p1;
                }
            }
        }
        CP_WAIT0();
        __syncthreads();
    }
}

// ---------------- K3: TWO warps per node (edges split) -> pool ---------------
__device__ __forceinline__ void red_add_v4(float* p, float4 v) {
    asm volatile("red.global.add.v4.f32 [%0], {%1, %2, %3, %4};"
                 :: "l"(p), "f"(v.x), "f"(v.y), "f"(v.z), "f"(v.w) : "memory");
}

__device__ __forceinline__ void acc_edge(float4& acc, const float4& a, uint2 rb) {
    float b0 = __int_as_float(rb.x << 16);
    float b1 = __int_as_float(rb.x & 0xffff0000u);
    float b2 = __int_as_float(rb.y << 16);
    float b3 = __int_as_float(rb.y & 0xffff0000u);
    acc.x += fmaxf(a.x + b0, 0.f);
    acc.y += fmaxf(a.y + b1, 0.f);
    acc.z += fmaxf(a.z + b2, 0.f);
    acc.w += fmaxf(a.w + b3, 0.f);
}

__global__ void __launch_bounds__(256) k3(const int* __restrict__ seg) {
    const int gw = (blockIdx.x * 256 + threadIdx.x) >> 5;
    const int i = gw >> 1;
    if (i >= NN) return;
    const int half = gw & 1;
    const int lane = threadIdx.x & 31;
    const int deg = min(g_cnt[i], PAD);
    const int e0 = half ? (deg >> 1) : 0;
    const int e1 = half ? deg : (deg >> 1);
    if (e0 >= e1) return;
    const float4 a = *(const float4*)&g_a[i * HH + lane * 4];
    const int g = __ldg(seg + i);
    const int* al = g_adj + i * PAD;
    float4 acc = make_float4(0.f, 0.f, 0.f, 0.f);
    int j = e0;
    for (; j + 8 <= e1; j += 8) {
        int d[8];
#pragma unroll
        for (int u = 0; u < 8; u++) d[u] = __ldg(al + j + u);
        uint2 rb[8];
#pragma unroll
        for (int u = 0; u < 8; u++)
            rb[u] = *(const uint2*)&g_bh[d[u] * 64 + lane * 2];
#pragma unroll
        for (int u = 0; u < 8; u++) acc_edge(acc, a, rb[u]);
    }
    for (; j < e1; j++) {
        int d = __ldg(al + j);
        uint2 rb = *(const uint2*)&g_bh[d * 64 + lane * 2];
        acc_edge(acc, a, rb);
    }
    red_add_v4(&g_p[g * HH + lane * 4], acc);
}

// ---------------- K4: y2 = p @ w_post + b_post ; double col sums -------------
__global__ void __launch_bounds__(128) k4(const float* __restrict__ wpost,
                                          const float* __restrict__ bpost) {
    extern __shared__ float ws4[];
    __shared__ float ps[HH];
    const int t = threadIdx.x;
    for (int i = t; i < HH * HH; i += 128) ws4[i] = wpost[i];
    const float bc = bpost[t];
    const int r0 = blockIdx.x * (GG / 128);
    double bsum = 0.0, bsq = 0.0;
    __syncthreads();
    for (int r = r0; r < r0 + GG / 128; r++) {
        __syncthreads();
        ps[t] = g_p[r * HH + t];
        __syncthreads();
        float A0 = 0.f, A1 = 0.f, A2 = 0.f, A3 = 0.f;
#pragma unroll 8
        for (int k = 0; k < HH; k += 4) {
            A0 = fmaf(ps[k + 0], ws4[(k + 0) * HH + t], A0);
            A1 = fmaf(ps[k + 1], ws4[(k + 1) * HH + t], A1);
            A2 = fmaf(ps[k + 2], ws4[(k + 2) * HH + t], A2);
            A3 = fmaf(ps[k + 3], ws4[(k + 3) * HH + t], A3);
        }
        float acc = ((A0 + A1) + (A2 + A3)) + bc;
        g_y2[r * HH + t] = acc;
        bsum += (double)acc;
        bsq = fma((double)acc, (double)acc, bsq);
    }
    atomicAdd(&g_sum2[t], bsum);
    atomicAdd(&g_sumsq2[t], bsq);
}

// ---------------- K5: relu(BN(y2)) @ w_out + b_out -> sigmoid ----------------
__global__ void __launch_bounds__(256) k5(const float* __restrict__ gpost,
                                          const float* __restrict__ bepost,
                                          const float* __restrict__ wout,
                                          const float* __restrict__ bout,
                                          float* __restrict__ out) {
    const int r = (blockIdx.x * 256 + threadIdx.x) >> 5;
    const int lane = threadIdx.x & 31;
    if (r >= GG) return;
    float acc = 0.f;
#pragma unroll
    for (int j = 0; j < 4; j++) {
        int c = lane + 32 * j;
        double mu = g_sum2[c] * (1.0 / GG);
        float var = (float)(g_sumsq2[c] * (1.0 / GG) - mu * mu);
        float sc = gpost[c] * rsqrtf(var + BN_EPSF);
        float hb = bepost[c] - (float)mu * sc;
        float hn = fmaxf(fmaf(g_y2[r * HH + c], sc, hb), 0.f);
        acc += hn * wout[c];
    }
#pragma unroll
    for (int o = 16; o; o >>= 1) acc += __shfl_down_sync(0xffffffffu, acc, o);
    if (lane == 0) out[r] = 1.f / (1.f + expf(-(acc + bout[0])));
}

// ---------------- launch -----------------------------------------------------
extern "C" void kernel_launch(void* const* d_in, const int* in_sizes, int n_in,
                              void* d_out, int out_size) {
    const float* x      = (const float*)d_in[0];
    const int*   src    = (const int*)d_in[1];
    const int*   dst    = (const int*)d_in[2];
    const int*   seg    = (const int*)d_in[3];
    const float* w_pre  = (const float*)d_in[4];
    const float* gm_pre = (const float*)d_in[6];
    const float* be_pre = (const float*)d_in[7];
    const float* w_cn   = (const float*)d_in[8];
    const float* b_cn   = (const float*)d_in[9];
    const float* w_post = (const float*)d_in[10];
    const float* b_post = (const float*)d_in[11];
    const float* gm_post= (const float*)d_in[12];
    const float* be_post= (const float*)d_in[13];
    const float* w_out  = (const float*)d_in[14];
    const float* b_out  = (const float*)d_in[15];
    float* out = (float*)d_out;
    const int E = in_sizes[1];

    static cudaStream_t s2 = nullptr;
    static cudaEvent_t ev_fork = nullptr, ev_join = nullptr;
    if (!s2) {
        cudaStreamCreateWithFlags(&s2, cudaStreamNonBlocking);
        cudaEventCreateWithFlags(&ev_fork, cudaEventDisableTiming);
        cudaEventCreateWithFlags(&ev_join, cudaEventDisableTiming);
    }

    const int k4_smem = HH * HH * 4;
    cudaFuncSetAttribute(kfused, cudaFuncAttributeMaxDynamicSharedMemorySize, KF_SMEM);
    cudaFuncSetAttribute(k4, cudaFuncAttributeMaxDynamicSharedMemorySize, k4_smem);

    // #1: zero everything
    kzero<<<(GG * HH + 255) / 256, 256>>>();
    // fork: adjacency build on s2, concurrent with kstat+kfused on main stream
    cudaEventRecord(ev_fork, 0);
    cudaStreamWaitEvent(s2, ev_fork, 0);
    kscat2<<<(E / 8 + 255) / 256, 256, 0, s2>>>(src, dst, E);   // #2
    cudaEventRecord(ev_join, s2);
    // main stream: BN stats from Gram matrix, then fused GEMM chain
    kstat<<<391, 256>>>(x);                                      // #3
    kfused<<<148, 512, KF_SMEM>>>(x, w_pre, gm_pre, be_pre, w_cn, b_cn); // #4
    // join: k3 needs adjacency + A/B
    cudaStreamWaitEvent(0, ev_join, 0);
    k3<<<(NN * 2 * 32 + 255) / 256, 256>>>(seg);                 // #5
    k4<<<128, 128, k4_smem>>>(w_post, b_post);                   // #6
    k5<<<(GG * 32) / 256, 256>>>(gm_post, be_post, w_out, b_out, out);
}